// round 4
// baseline (speedup 1.0000x reference)
#include <cuda_runtime.h>
#include <math.h>

#define Bsz   2
#define Ssz   2048
#define INDIM 1024
#define EMB   1024
#define NH    16
#define HD    64
#define PADW  128

#define M1 (Bsz*Ssz)   /* 4096 */
#define N1 (3*EMB)     /* 3072 */

// Scratch (static device globals — no runtime allocation)
__device__ float g_q[Bsz*NH*Ssz*HD];
__device__ float g_k[Bsz*NH*Ssz*HD];
__device__ float g_v[Bsz*NH*Ssz*HD];
__device__ float g_vals[M1*EMB];

// ---------------------------------------------------------------------------
// Kernel 1: QKV projection  C[m][n] = sum_k x[m][k] * Wqkv[n][k] + bqkv[n]
// then mask (padding_mask==1 -> 0) and scatter into g_q/g_k/g_v [B,H,S,hd].
// 128x128 tile, BK=16, 8x8 micro-tile, 256 threads.
// ---------------------------------------------------------------------------
__global__ __launch_bounds__(256) void qkv_gemm(
    const float* __restrict__ A,     // x [4096,1024]
    const float* __restrict__ Bw,    // Wqkv [3072,1024]
    const float* __restrict__ bias,  // bqkv [3072]
    const int*   __restrict__ pm)    // padding_mask [4096]
{
    __shared__ float As[16][132];
    __shared__ float Bs[16][132];
    const int t  = threadIdx.x;
    const int tx = t & 15, ty = t >> 4;
    const int m0 = blockIdx.y * 128, n0 = blockIdx.x * 128;

    float acc[8][8] = {};

    for (int k0 = 0; k0 < INDIM; k0 += 16) {
        #pragma unroll
        for (int i = 0; i < 2; i++) {
            int v   = t + i * 256;
            int row = v >> 2;
            int kc  = (v & 3) << 2;
            float4 a4 = *reinterpret_cast<const float4*>(A  + (size_t)(m0 + row) * INDIM + k0 + kc);
            As[kc + 0][row] = a4.x; As[kc + 1][row] = a4.y;
            As[kc + 2][row] = a4.z; As[kc + 3][row] = a4.w;
            float4 b4 = *reinterpret_cast<const float4*>(Bw + (size_t)(n0 + row) * INDIM + k0 + kc);
            Bs[kc + 0][row] = b4.x; Bs[kc + 1][row] = b4.y;
            Bs[kc + 2][row] = b4.z; Bs[kc + 3][row] = b4.w;
        }
        __syncthreads();
        #pragma unroll
        for (int kk = 0; kk < 16; kk++) {
            float a[8], b[8];
            *reinterpret_cast<float4*>(a)     = *reinterpret_cast<const float4*>(&As[kk][ty * 8]);
            *reinterpret_cast<float4*>(a + 4) = *reinterpret_cast<const float4*>(&As[kk][ty * 8 + 4]);
            *reinterpret_cast<float4*>(b)     = *reinterpret_cast<const float4*>(&Bs[kk][tx * 8]);
            *reinterpret_cast<float4*>(b + 4) = *reinterpret_cast<const float4*>(&Bs[kk][tx * 8 + 4]);
            #pragma unroll
            for (int i = 0; i < 8; i++)
                #pragma unroll
                for (int j = 0; j < 8; j++)
                    acc[i][j] = fmaf(a[i], b[j], acc[i][j]);
        }
        __syncthreads();
    }

    // Epilogue: bias + padding mask + scatter to q/k/v
    #pragma unroll
    for (int i = 0; i < 8; i++) {
        int m = m0 + ty * 8 + i;
        int b = m >> 11;         // m / 2048
        int s = m & 2047;
        int msk = pm[m];
        #pragma unroll
        for (int j = 0; j < 8; j++) {
            int n = n0 + tx * 8 + j;
            float val = msk ? 0.0f : (acc[i][j] + bias[n]);
            int h = n / 192;               // head
            int c = n - h * 192;           // 0..191: [q|k|v] within head
            int base = ((b * NH + h) * Ssz + s) * HD;
            if (c < HD)           g_q[base + c]         = val;
            else if (c < 2 * HD)  g_k[base + c - HD]    = val;
            else                  g_v[base + c - 2*HD]  = val;
        }
    }
}

// ---------------------------------------------------------------------------
// Kernel 2: banded attention. One block per (b, h, 64-query tile).
// Score strip is 320 keys wide: cols c map to key j = qs-128+c.
// Band validity: c in [r, r+256] and 0 <= j < S.   (out-of-band exp == 0
// exactly in the reference due to fp32 underflow of exp(-1.125e15 - max))
// ---------------------------------------------------------------------------
#define SW 328   // padded score stride

__global__ __launch_bounds__(256) void attn_kernel()
{
    extern __shared__ float sm[];
    float* q_s   = sm;                    // 64 x 68
    float* kv_s  = sm + 64 * 68;          // 64 x 68
    float* sc    = kv_s + 64 * 68;        // 64 x SW
    float* inv_s = sc + 64 * SW;          // 64

    const int t  = threadIdx.x;
    const int tx = t & 15, ty = t >> 4;
    const int bh = blockIdx.y;
    const int b  = bh >> 4, h = bh & 15;
    const int qs = blockIdx.x * 64;
    const int kb = qs - PADW;

    const float* qp = g_q + (size_t)(b * NH + h) * Ssz * HD;
    const float* kp = g_k + (size_t)(b * NH + h) * Ssz * HD;
    const float* vp = g_v + (size_t)(b * NH + h) * Ssz * HD;

    // Load Q tile (64 x 64)
    #pragma unroll
    for (int i = 0; i < 4; i++) {
        int v   = t + i * 256;
        int row = v >> 4;
        int c4  = (v & 15) << 2;
        *reinterpret_cast<float4*>(&q_s[row * 68 + c4]) =
            *reinterpret_cast<const float4*>(qp + (size_t)(qs + row) * HD + c4);
    }

    // ---- Score phase: 5 key chunks of 64 ----
    for (int ch = 0; ch < 5; ch++) {
        __syncthreads();
        #pragma unroll
        for (int i = 0; i < 4; i++) {
            int v   = t + i * 256;
            int row = v >> 4;
            int c4  = (v & 15) << 2;
            int j   = kb + ch * 64 + row;
            float4 val = make_float4(0.f, 0.f, 0.f, 0.f);
            if (j >= 0 && j < Ssz)
                val = *reinterpret_cast<const float4*>(kp + (size_t)j * HD + c4);
            *reinterpret_cast<float4*>(&kv_s[row * 68 + c4]) = val;
        }
        __syncthreads();

        float accs[4][4] = {};
        #pragma unroll
        for (int kk = 0; kk < 64; kk += 4) {
            float4 av[4], bv[4];
            #pragma unroll
            for (int i = 0; i < 4; i++)
                av[i] = *reinterpret_cast<const float4*>(&q_s[(ty * 4 + i) * 68 + kk]);
            #pragma unroll
            for (int j = 0; j < 4; j++)
                bv[j] = *reinterpret_cast<const float4*>(&kv_s[(tx * 4 + j) * 68 + kk]);
            #pragma unroll
            for (int i = 0; i < 4; i++)
                #pragma unroll
                for (int j = 0; j < 4; j++)
                    accs[i][j] += av[i].x * bv[j].x + av[i].y * bv[j].y
                                + av[i].z * bv[j].z + av[i].w * bv[j].w;
        }
        #pragma unroll
        for (int i = 0; i < 4; i++) {
            float4 st = make_float4(accs[i][0], accs[i][1], accs[i][2], accs[i][3]);
            *reinterpret_cast<float4*>(&sc[(ty * 4 + i) * SW + ch * 64 + tx * 4]) = st;
        }
    }
    __syncthreads();

    // ---- Softmax over the 320-wide band strip (4 lanes per query row) ----
    {
        const int r = t >> 2, g = t & 3;
        const float scale = 0.125f;   // 1/sqrt(64)
        float mx = -1e30f;
        for (int c = g; c < 320; c += 4) {
            int j = kb + c;
            if (j >= 0 && j < Ssz && c >= r && c <= r + 256)
                mx = fmaxf(mx, sc[r * SW + c]);
        }
        mx = fmaxf(mx, __shfl_xor_sync(0xffffffffu, mx, 1));
        mx = fmaxf(mx, __shfl_xor_sync(0xffffffffu, mx, 2));
        float mxs = mx * scale;
        float sum = 0.f;
        for (int c = g; c < 320; c += 4) {
            int j = kb + c;
            float e = 0.f;
            if (j >= 0 && j < Ssz && c >= r && c <= r + 256)
                e = __expf(sc[r * SW + c] * scale - mxs);
            sc[r * SW + c] = e;
            sum += e;
        }
        sum += __shfl_xor_sync(0xffffffffu, sum, 1);
        sum += __shfl_xor_sync(0xffffffffu, sum, 2);
        if (g == 0) inv_s[r] = 1.0f / sum;
    }

    // ---- PV phase: out[64 x 64] += P[64 x 320] @ V[320 x 64] ----
    float outr[4][4] = {};
    for (int ch = 0; ch < 5; ch++) {
        __syncthreads();
        #pragma unroll
        for (int i = 0; i < 4; i++) {
            int v   = t + i * 256;
            int row = v >> 4;
            int c4  = (v & 15) << 2;
            int j   = kb + ch * 64 + row;
            float4 val = make_float4(0.f, 0.f, 0.f, 0.f);
            if (j >= 0 && j < Ssz)
                val = *reinterpret_cast<const float4*>(vp + (size_t)j * HD + c4);
            *reinterpret_cast<float4*>(&kv_s[row * 68 + c4]) = val;
        }
        __syncthreads();

        #pragma unroll 8
        for (int kk = 0; kk < 64; kk++) {
            float4 vv = *reinterpret_cast<const float4*>(&kv_s[kk * 68 + tx * 4]);
            #pragma unroll
            for (int i = 0; i < 4; i++) {
                float p = sc[(ty * 4 + i) * SW + ch * 64 + kk];
                outr[i][0] = fmaf(p, vv.x, outr[i][0]);
                outr[i][1] = fmaf(p, vv.y, outr[i][1]);
                outr[i][2] = fmaf(p, vv.z, outr[i][2]);
                outr[i][3] = fmaf(p, vv.w, outr[i][3]);
            }
        }
    }

    // ---- Write normalized output into g_vals [B,S,E] ----
    #pragma unroll
    for (int i = 0; i < 4; i++) {
        int r = ty * 4 + i;
        float is = inv_s[r];
        float4 o = make_float4(outr[i][0] * is, outr[i][1] * is,
                               outr[i][2] * is, outr[i][3] * is);
        *reinterpret_cast<float4*>(
            &g_vals[(size_t)(b * Ssz + qs + r) * EMB + h * HD + tx * 4]) = o;
    }
}

// ---------------------------------------------------------------------------
// Kernel 3: output projection  out[m][n] = sum_k vals[m][k]*Wo[n][k] + bo[n]
// ---------------------------------------------------------------------------
__global__ __launch_bounds__(256) void out_gemm(
    const float* __restrict__ Bw,    // Wo [1024,1024]
    const float* __restrict__ bias,  // bo [1024]
    float* __restrict__ C)           // out [4096,1024]
{
    __shared__ float As[16][132];
    __shared__ float Bs[16][132];
    const float* A = g_vals;
    const int t  = threadIdx.x;
    const int tx = t & 15, ty = t >> 4;
    const int m0 = blockIdx.y * 128, n0 = blockIdx.x * 128;

    float acc[8][8] = {};

    for (int k0 = 0; k0 < EMB; k0 += 16) {
        #pragma unroll
        for (int i = 0; i < 2; i++) {
            int v   = t + i * 256;
            int row = v >> 2;
            int kc  = (v & 3) << 2;
            float4 a4 = *reinterpret_cast<const float4*>(A  + (size_t)(m0 + row) * EMB + k0 + kc);
            As[kc + 0][row] = a4.x; As[kc + 1][row] = a4.y;
            As[kc + 2][row] = a4.z; As[kc + 3][row] = a4.w;
            float4 b4 = *reinterpret_cast<const float4*>(Bw + (size_t)(n0 + row) * EMB + k0 + kc);
            Bs[kc + 0][row] = b4.x; Bs[kc + 1][row] = b4.y;
            Bs[kc + 2][row] = b4.z; Bs[kc + 3][row] = b4.w;
        }
        __syncthreads();
        #pragma unroll
        for (int kk = 0; kk < 16; kk++) {
            float a[8], b[8];
            *reinterpret_cast<float4*>(a)     = *reinterpret_cast<const float4*>(&As[kk][ty * 8]);
            *reinterpret_cast<float4*>(a + 4) = *reinterpret_cast<const float4*>(&As[kk][ty * 8 + 4]);
            *reinterpret_cast<float4*>(b)     = *reinterpret_cast<const float4*>(&Bs[kk][tx * 8]);
            *reinterpret_cast<float4*>(b + 4) = *reinterpret_cast<const float4*>(&Bs[kk][tx * 8 + 4]);
            #pragma unroll
            for (int i = 0; i < 8; i++)
                #pragma unroll
                for (int j = 0; j < 8; j++)
                    acc[i][j] = fmaf(a[i], b[j], acc[i][j]);
        }
        __syncthreads();
    }

    #pragma unroll
    for (int i = 0; i < 8; i++) {
        int m = m0 + ty * 8 + i;
        #pragma unroll
        for (int j = 0; j < 8; j++) {
            int n = n0 + tx * 8 + j;
            C[(size_t)m * EMB + n] = acc[i][j] + bias[n];
        }
    }
}

// ---------------------------------------------------------------------------
extern "C" void kernel_launch(void* const* d_in, const int* in_sizes, int n_in,
                              void* d_out, int out_size)
{
    const float* x    = (const float*)d_in[0];
    const int*   pm   = (const int*)  d_in[1];
    const float* Wqkv = (const float*)d_in[2];
    const float* bqkv = (const float*)d_in[3];
    const float* Wo   = (const float*)d_in[4];
    const float* bo   = (const float*)d_in[5];
    float* out = (float*)d_out;

    const int attn_smem = (64 * 68 * 2 + 64 * SW + 64) * 4;  // 119040 B
    cudaFuncSetAttribute(attn_kernel,
                         cudaFuncAttributeMaxDynamicSharedMemorySize, attn_smem);

    qkv_gemm<<<dim3(N1 / 128, M1 / 128), 256>>>(x, Wqkv, bqkv, pm);
    attn_kernel<<<dim3(Ssz / 64, Bsz * NH), 256, attn_smem>>>();
    out_gemm<<<dim3(EMB / 128, M1 / 128), 256>>>(Wo, bo, out);
}

// round 7
// speedup vs baseline: 1.8561x; 1.8561x over previous
#include <cuda_runtime.h>
#include <cuda_bf16.h>
#include <math.h>
#include <cstdint>

#define Bsz   2
#define Ssz   2048
#define INDIM 1024
#define EMB   1024
#define NH    16
#define HD    64
#define PADW  128

#define M1 (Bsz*Ssz)   /* 4096 */
#define N1 (3*EMB)     /* 3072 */

// ---------------------------------------------------------------------------
// Baseline-ISA PTX helpers (all legal on compute_103 — no 'a'-only features)
// ---------------------------------------------------------------------------
__device__ __forceinline__ uint32_t smem_to_u32(const void* p) {
    uint32_t a;
    asm("{ .reg .u64 t; cvta.to.shared.u64 t, %1; cvt.u32.u64 %0, t; }" : "=r"(a) : "l"(p));
    return a;
}
#define CP_ASYNC16(saddr, gptr) \
    asm volatile("cp.async.cg.shared.global [%0], [%1], 16;" :: "r"(saddr), "l"(gptr))
#define CP_COMMIT() asm volatile("cp.async.commit_group;" ::: "memory")
#define CP_WAIT1()  asm volatile("cp.async.wait_group 1;" ::: "memory")
#define CP_WAIT0()  asm volatile("cp.async.wait_group 0;" ::: "memory")

__device__ __forceinline__ void ldm_x4(uint32_t* r, uint32_t addr) {
    asm volatile("ldmatrix.sync.aligned.m8n8.x4.shared.b16 {%0,%1,%2,%3}, [%4];"
        : "=r"(r[0]), "=r"(r[1]), "=r"(r[2]), "=r"(r[3]) : "r"(addr));
}
__device__ __forceinline__ void mma_bf16(float* d, const uint32_t* a, const uint32_t* b) {
    asm volatile("mma.sync.aligned.m16n8k16.row.col.f32.bf16.bf16.f32 "
        "{%0,%1,%2,%3}, {%4,%5,%6,%7}, {%8,%9}, {%0,%1,%2,%3};"
        : "+f"(d[0]), "+f"(d[1]), "+f"(d[2]), "+f"(d[3])
        : "r"(a[0]), "r"(a[1]), "r"(a[2]), "r"(a[3]), "r"(b[0]), "r"(b[1]));
}

// ---------------------------------------------------------------------------
// Scratch (static device globals)
// ---------------------------------------------------------------------------
__device__ float g_q[Bsz*NH*Ssz*HD];
__device__ float g_k[Bsz*NH*Ssz*HD];
__device__ float g_v[Bsz*NH*Ssz*HD];
__device__ float g_vals[M1*EMB];
__device__ __nv_bfloat16 g_xh[M1*INDIM],  g_xl[M1*INDIM];
__device__ __nv_bfloat16 g_wh[N1*INDIM],  g_wl[N1*INDIM];
__device__ __nv_bfloat16 g_woh[EMB*EMB],  g_wol[EMB*EMB];
__device__ __nv_bfloat16 g_vh[M1*EMB],    g_vl[M1*EMB];

// ---------------------------------------------------------------------------
// fp32 -> bf16 hi/lo split kernels
// ---------------------------------------------------------------------------
__device__ __forceinline__ void split4_store(const float4 f,
                                             __nv_bfloat162* hi, __nv_bfloat162* lo, int i)
{
    __nv_bfloat16 h0 = __float2bfloat16(f.x), h1 = __float2bfloat16(f.y);
    __nv_bfloat16 h2 = __float2bfloat16(f.z), h3 = __float2bfloat16(f.w);
    hi[2*i]   = __halves2bfloat162(h0, h1);
    hi[2*i+1] = __halves2bfloat162(h2, h3);
    lo[2*i]   = __halves2bfloat162(__float2bfloat16(f.x - __bfloat162float(h0)),
                                   __float2bfloat16(f.y - __bfloat162float(h1)));
    lo[2*i+1] = __halves2bfloat162(__float2bfloat16(f.z - __bfloat162float(h2)),
                                   __float2bfloat16(f.w - __bfloat162float(h3)));
}
__global__ void split_x(const float4* __restrict__ in) {
    int i = blockIdx.x * blockDim.x + threadIdx.x;
    if (i < (M1*INDIM)/4)
        split4_store(in[i], (__nv_bfloat162*)g_xh, (__nv_bfloat162*)g_xl, i);
}
__global__ void split_w(const float4* __restrict__ in) {
    int i = blockIdx.x * blockDim.x + threadIdx.x;
    if (i < (N1*INDIM)/4)
        split4_store(in[i], (__nv_bfloat162*)g_wh, (__nv_bfloat162*)g_wl, i);
}
__global__ void split_wo(const float4* __restrict__ in) {
    int i = blockIdx.x * blockDim.x + threadIdx.x;
    if (i < (EMB*EMB)/4)
        split4_store(in[i], (__nv_bfloat162*)g_woh, (__nv_bfloat162*)g_wol, i);
}
__global__ void split_vals() {
    int i = blockIdx.x * blockDim.x + threadIdx.x;
    if (i < (M1*EMB)/4)
        split4_store(((const float4*)g_vals)[i], (__nv_bfloat162*)g_vh, (__nv_bfloat162*)g_vl, i);
}

// ---------------------------------------------------------------------------
// HMMA GEMM (D = A @ B^T, A [M][1024], B [N][1024], both row-major bf16 split).
// CTA 128x128, BK=32, 8 warps (warp tile 64x32), double-buffered cp.async.
// Smem rows padded to 40 bf16 (80 B) -> conflict-free ldmatrix.
// ---------------------------------------------------------------------------
#define TILE_B 10240   /* 128 rows * 80 B */
#define GEMM_SMEM (8 * TILE_B)   /* 2 buffers x {Ah,Al,Bh,Bl} = 81920 B */

__device__ __forceinline__ void load4_async(
    const __nv_bfloat16* ah, const __nv_bfloat16* al,
    const __nv_bfloat16* bh, const __nv_bfloat16* bl,
    int m0, int n0, int k0, uint32_t sb, int buf, int t)
{
    uint32_t base = sb + buf * 4 * TILE_B;
    #pragma unroll
    for (int i = 0; i < 2; i++) {
        int c  = t + i * 256;     // 0..511
        int r  = c >> 2;
        int kc = c & 3;
        size_t goffA = (size_t)(m0 + r) * 1024 + k0 + kc * 8;
        size_t goffB = (size_t)(n0 + r) * 1024 + k0 + kc * 8;
        uint32_t soff = (uint32_t)(r * 80 + kc * 16);
        CP_ASYNC16(base + 0*TILE_B + soff, ah + goffA);
        CP_ASYNC16(base + 1*TILE_B + soff, al + goffA);
        CP_ASYNC16(base + 2*TILE_B + soff, bh + goffB);
        CP_ASYNC16(base + 3*TILE_B + soff, bl + goffB);
    }
}

__device__ __forceinline__ void gemm_mainloop(
    const __nv_bfloat16* __restrict__ ah, const __nv_bfloat16* __restrict__ al,
    const __nv_bfloat16* __restrict__ bh, const __nv_bfloat16* __restrict__ bl,
    int m0, int n0, uint32_t sb, int t, float acc[4][4][4])
{
    const int lane = t & 31, wid = t >> 5;
    const int wm = (wid >> 2) * 64, wn = (wid & 3) * 32;

    #pragma unroll
    for (int a = 0; a < 4; a++)
        #pragma unroll
        for (int b = 0; b < 4; b++)
            #pragma unroll
            for (int e = 0; e < 4; e++)
                acc[a][b][e] = 0.f;

    load4_async(ah, al, bh, bl, m0, n0, 0, sb, 0, t);
    CP_COMMIT();

    const int arow = wm + (lane & 15);
    const int akd  = (lane & 16) >> 1;         // +8 k for lanes 16-31
    const int nrow = wn + (lane & 7) + ((lane & 16) >> 1);
    const int bkd  = (lane & 8);               // +8 k for lanes 8-15,24-31

    for (int ch = 0; ch < 32; ch++) {
        const int b = ch & 1;
        if (ch + 1 < 32) {
            load4_async(ah, al, bh, bl, m0, n0, (ch + 1) * 32, sb, 1 - b, t);
            CP_COMMIT();
            CP_WAIT1();
        } else {
            CP_WAIT0();
        }
        __syncthreads();

        const uint32_t base = sb + b * 4 * TILE_B;
        #pragma unroll
        for (int ks = 0; ks < 2; ks++) {
            const int kk = ks * 16;
            uint32_t ahf[4][4], alf[4][4], bhf[2][4], blf[2][4];
            #pragma unroll
            for (int mt = 0; mt < 4; mt++) {
                uint32_t off = (uint32_t)((arow + mt * 16) * 80 + (kk + akd) * 2);
                ldm_x4(ahf[mt], base + 0*TILE_B + off);
                ldm_x4(alf[mt], base + 1*TILE_B + off);
            }
            #pragma unroll
            for (int g = 0; g < 2; g++) {
                uint32_t off = (uint32_t)((nrow + g * 16) * 80 + (kk + bkd) * 2);
                ldm_x4(bhf[g], base + 2*TILE_B + off);
                ldm_x4(blf[g], base + 3*TILE_B + off);
            }
            #pragma unroll
            for (int mt = 0; mt < 4; mt++)
                #pragma unroll
                for (int nt = 0; nt < 4; nt++) {
                    const uint32_t* b2h = &bhf[nt >> 1][(nt & 1) * 2];
                    const uint32_t* b2l = &blf[nt >> 1][(nt & 1) * 2];
                    mma_bf16(acc[mt][nt], ahf[mt], b2h);
                    mma_bf16(acc[mt][nt], ahf[mt], b2l);
                    mma_bf16(acc[mt][nt], alf[mt], b2h);
                }
        }
        __syncthreads();
    }
}

// QKV projection with bias + padding mask + scatter epilogue
__global__ __launch_bounds__(256) void qkv_mma(
    const float* __restrict__ bias, const int* __restrict__ pm)
{
    extern __shared__ __align__(16) char smem[];
    const uint32_t sb = smem_to_u32(smem);
    const int t = threadIdx.x, lane = t & 31, wid = t >> 5;
    const int wm = (wid >> 2) * 64, wn = (wid & 3) * 32;
    const int n0 = blockIdx.x * 128, m0 = blockIdx.y * 128;

    float acc[4][4][4];
    gemm_mainloop(g_xh, g_xl, g_wh, g_wl, m0, n0, sb, t, acc);

    const int lr = lane >> 2, lc = (lane & 3) * 2;
    #pragma unroll
    for (int mt = 0; mt < 4; mt++) {
        #pragma unroll
        for (int half = 0; half < 2; half++) {
            const int m = m0 + wm + mt * 16 + lr + half * 8;
            const int msk = pm[m];
            const int bb = m >> 11, s = m & 2047;
            #pragma unroll
            for (int nt = 0; nt < 4; nt++) {
                #pragma unroll
                for (int e = 0; e < 2; e++) {
                    const int n = n0 + wn + nt * 8 + lc + e;
                    float val = msk ? 0.0f : (acc[mt][nt][half * 2 + e] + bias[n]);
                    int h  = n / 192;
                    int cc = n - h * 192;
                    int gb = ((bb * NH + h) * Ssz + s) * HD;
                    if (cc < HD)          g_q[gb + cc]          = val;
                    else if (cc < 2*HD)   g_k[gb + cc - HD]     = val;
                    else                  g_v[gb + cc - 2*HD]   = val;
                }
            }
        }
    }
}

// Output projection: out = vals @ Wo^T + bo
__global__ __launch_bounds__(256) void out_mma(
    const float* __restrict__ bias, float* __restrict__ C)
{
    extern __shared__ __align__(16) char smem[];
    const uint32_t sb = smem_to_u32(smem);
    const int t = threadIdx.x, lane = t & 31, wid = t >> 5;
    const int wm = (wid >> 2) * 64, wn = (wid & 3) * 32;
    const int n0 = blockIdx.x * 128, m0 = blockIdx.y * 128;

    float acc[4][4][4];
    gemm_mainloop(g_vh, g_vl, g_woh, g_wol, m0, n0, sb, t, acc);

    const int lr = lane >> 2, lc = (lane & 3) * 2;
    #pragma unroll
    for (int mt = 0; mt < 4; mt++) {
        #pragma unroll
        for (int half = 0; half < 2; half++) {
            const int m = m0 + wm + mt * 16 + lr + half * 8;
            #pragma unroll
            for (int nt = 0; nt < 4; nt++) {
                const int n = n0 + wn + nt * 8 + lc;
                float2 o;
                o.x = acc[mt][nt][half * 2 + 0] + bias[n];
                o.y = acc[mt][nt][half * 2 + 1] + bias[n + 1];
                *reinterpret_cast<float2*>(C + (size_t)m * EMB + n) = o;
            }
        }
    }
}

// ---------------------------------------------------------------------------
// Banded attention (unchanged, validated round-4 kernel)
// ---------------------------------------------------------------------------
#define SW 328

__global__ __launch_bounds__(256) void attn_kernel()
{
    extern __shared__ float sm[];
    float* q_s   = sm;
    float* kv_s  = sm + 64 * 68;
    float* sc    = kv_s + 64 * 68;
    float* inv_s = sc + 64 * SW;

    const int t  = threadIdx.x;
    const int tx = t & 15, ty = t >> 4;
    const int bh = blockIdx.y;
    const int b  = bh >> 4, h = bh & 15;
    const int qs = blockIdx.x * 64;
    const int kb = qs - PADW;

    const float* qp = g_q + (size_t)(b * NH + h) * Ssz * HD;
    const float* kp = g_k + (size_t)(b * NH + h) * Ssz * HD;
    const float* vp = g_v + (size_t)(b * NH + h) * Ssz * HD;

    #pragma unroll
    for (int i = 0; i < 4; i++) {
        int v   = t + i * 256;
        int row = v >> 4;
        int c4  = (v & 15) << 2;
        *reinterpret_cast<float4*>(&q_s[row * 68 + c4]) =
            *reinterpret_cast<const float4*>(qp + (size_t)(qs + row) * HD + c4);
    }

    for (int ch = 0; ch < 5; ch++) {
        __syncthreads();
        #pragma unroll
        for (int i = 0; i < 4; i++) {
            int v   = t + i * 256;
            int row = v >> 4;
            int c4  = (v & 15) << 2;
            int j   = kb + ch * 64 + row;
            float4 val = make_float4(0.f, 0.f, 0.f, 0.f);
            if (j >= 0 && j < Ssz)
                val = *reinterpret_cast<const float4*>(kp + (size_t)j * HD + c4);
            *reinterpret_cast<float4*>(&kv_s[row * 68 + c4]) = val;
        }
        __syncthreads();

        float accs[4][4] = {};
        #pragma unroll
        for (int kk = 0; kk < 64; kk += 4) {
            float4 av[4], bv[4];
            #pragma unroll
            for (int i = 0; i < 4; i++)
                av[i] = *reinterpret_cast<const float4*>(&q_s[(ty * 4 + i) * 68 + kk]);
            #pragma unroll
            for (int j = 0; j < 4; j++)
                bv[j] = *reinterpret_cast<const float4*>(&kv_s[(tx * 4 + j) * 68 + kk]);
            #pragma unroll
            for (int i = 0; i < 4; i++)
                #pragma unroll
                for (int j = 0; j < 4; j++)
                    accs[i][j] += av[i].x * bv[j].x + av[i].y * bv[j].y
                                + av[i].z * bv[j].z + av[i].w * bv[j].w;
        }
        #pragma unroll
        for (int i = 0; i < 4; i++) {
            float4 st = make_float4(accs[i][0], accs[i][1], accs[i][2], accs[i][3]);
            *reinterpret_cast<float4*>(&sc[(ty * 4 + i) * SW + ch * 64 + tx * 4]) = st;
        }
    }
    __syncthreads();

    {
        const int r = t >> 2, g = t & 3;
        const float scale = 0.125f;
        float mx = -1e30f;
        for (int c = g; c < 320; c += 4) {
            int j = kb + c;
            if (j >= 0 && j < Ssz && c >= r && c <= r + 256)
                mx = fmaxf(mx, sc[r * SW + c]);
        }
        mx = fmaxf(mx, __shfl_xor_sync(0xffffffffu, mx, 1));
        mx = fmaxf(mx, __shfl_xor_sync(0xffffffffu, mx, 2));
        float mxs = mx * scale;
        float sum = 0.f;
        for (int c = g; c < 320; c += 4) {
            int j = kb + c;
            float e = 0.f;
            if (j >= 0 && j < Ssz && c >= r && c <= r + 256)
                e = __expf(sc[r * SW + c] * scale - mxs);
            sc[r * SW + c] = e;
            sum += e;
        }
        sum += __shfl_xor_sync(0xffffffffu, sum, 1);
        sum += __shfl_xor_sync(0xffffffffu, sum, 2);
        if (g == 0) inv_s[r] = 1.0f / sum;
    }

    float outr[4][4] = {};
    for (int ch = 0; ch < 5; ch++) {
        __syncthreads();
        #pragma unroll
        for (int i = 0; i < 4; i++) {
            int v   = t + i * 256;
            int row = v >> 4;
            int c4  = (v & 15) << 2;
            int j   = kb + ch * 64 + row;
            float4 val = make_float4(0.f, 0.f, 0.f, 0.f);
            if (j >= 0 && j < Ssz)
                val = *reinterpret_cast<const float4*>(vp + (size_t)j * HD + c4);
            *reinterpret_cast<float4*>(&kv_s[row * 68 + c4]) = val;
        }
        __syncthreads();

        #pragma unroll 8
        for (int kk = 0; kk < 64; kk++) {
            float4 vv = *reinterpret_cast<const float4*>(&kv_s[kk * 68 + tx * 4]);
            #pragma unroll
            for (int i = 0; i < 4; i++) {
                float p = sc[(ty * 4 + i) * SW + ch * 64 + kk];
                outr[i][0] = fmaf(p, vv.x, outr[i][0]);
                outr[i][1] = fmaf(p, vv.y, outr[i][1]);
                outr[i][2] = fmaf(p, vv.z, outr[i][2]);
                outr[i][3] = fmaf(p, vv.w, outr[i][3]);
            }
        }
    }

    #pragma unroll
    for (int i = 0; i < 4; i++) {
        int r = ty * 4 + i;
        float is = inv_s[r];
        float4 o = make_float4(outr[i][0] * is, outr[i][1] * is,
                               outr[i][2] * is, outr[i][3] * is);
        *reinterpret_cast<float4*>(
            &g_vals[(size_t)(b * Ssz + qs + r) * EMB + h * HD + tx * 4]) = o;
    }
}

// ---------------------------------------------------------------------------
extern "C" void kernel_launch(void* const* d_in, const int* in_sizes, int n_in,
                              void* d_out, int out_size)
{
    const float* x    = (const float*)d_in[0];
    const int*   pm   = (const int*)  d_in[1];
    const float* Wqkv = (const float*)d_in[2];
    const float* bqkv = (const float*)d_in[3];
    const float* Wo   = (const float*)d_in[4];
    const float* bo   = (const float*)d_in[5];
    float* out = (float*)d_out;

    const int attn_smem = (64 * 68 * 2 + 64 * SW + 64) * 4;
    cudaFuncSetAttribute(attn_kernel,
                         cudaFuncAttributeMaxDynamicSharedMemorySize, attn_smem);
    cudaFuncSetAttribute(qkv_mma,
                         cudaFuncAttributeMaxDynamicSharedMemorySize, GEMM_SMEM);
    cudaFuncSetAttribute(out_mma,
                         cudaFuncAttributeMaxDynamicSharedMemorySize, GEMM_SMEM);

    split_x <<<(M1*INDIM/4 + 255)/256, 256>>>((const float4*)x);
    split_w <<<(N1*INDIM/4 + 255)/256, 256>>>((const float4*)Wqkv);
    split_wo<<<(EMB*EMB/4  + 255)/256, 256>>>((const float4*)Wo);

    qkv_mma<<<dim3(N1/128, M1/128), 256, GEMM_SMEM>>>(bqkv, pm);

    attn_kernel<<<dim3(Ssz/64, Bsz*NH), 256, attn_smem>>>();

    split_vals<<<(M1*EMB/4 + 255)/256, 256>>>();

    out_mma<<<dim3(EMB/128, M1/128), 256, GEMM_SMEM>>>(bo, out);
}

// round 8
// speedup vs baseline: 2.4025x; 1.2944x over previous
#include <cuda_runtime.h>
#include <cuda_bf16.h>
#include <math.h>
#include <cstdint>

#define Bsz   2
#define Ssz   2048
#define INDIM 1024
#define EMB   1024
#define NH    16
#define HD    64
#define PADW  128

#define M1 (Bsz*Ssz)   /* 4096 */
#define N1 (3*EMB)     /* 3072 */

// ---------------------------------------------------------------------------
// Baseline-ISA PTX helpers (compute_103-legal)
// ---------------------------------------------------------------------------
__device__ __forceinline__ uint32_t smem_to_u32(const void* p) {
    uint32_t a;
    asm("{ .reg .u64 t; cvta.to.shared.u64 t, %1; cvt.u32.u64 %0, t; }" : "=r"(a) : "l"(p));
    return a;
}
#define CP_ASYNC16(saddr, gptr) \
    asm volatile("cp.async.cg.shared.global [%0], [%1], 16;" :: "r"(saddr), "l"(gptr))
#define CP_COMMIT() asm volatile("cp.async.commit_group;" ::: "memory")
#define CP_WAIT1()  asm volatile("cp.async.wait_group 1;" ::: "memory")
#define CP_WAIT0()  asm volatile("cp.async.wait_group 0;" ::: "memory")

__device__ __forceinline__ void ldm_x4(uint32_t* r, uint32_t addr) {
    asm volatile("ldmatrix.sync.aligned.m8n8.x4.shared.b16 {%0,%1,%2,%3}, [%4];"
        : "=r"(r[0]), "=r"(r[1]), "=r"(r[2]), "=r"(r[3]) : "r"(addr));
}
__device__ __forceinline__ void mma_bf16(float* d, const uint32_t* a, const uint32_t* b) {
    asm volatile("mma.sync.aligned.m16n8k16.row.col.f32.bf16.bf16.f32 "
        "{%0,%1,%2,%3}, {%4,%5,%6,%7}, {%8,%9}, {%0,%1,%2,%3};"
        : "+f"(d[0]), "+f"(d[1]), "+f"(d[2]), "+f"(d[3])
        : "r"(a[0]), "r"(a[1]), "r"(a[2]), "r"(a[3]), "r"(b[0]), "r"(b[1]));
}

// ---------------------------------------------------------------------------
// Scratch (static device globals, all bf16 except none)
// ---------------------------------------------------------------------------
__device__ __nv_bfloat16 g_xh[M1*INDIM],  g_xl[M1*INDIM];
__device__ __nv_bfloat16 g_wh[N1*INDIM],  g_wl[N1*INDIM];
__device__ __nv_bfloat16 g_woh[EMB*EMB],  g_wol[EMB*EMB];
// q,k: [b,h,s,d]; v transposed: [b,h,d,s]
__device__ __nv_bfloat16 g_qh[Bsz*NH*Ssz*HD], g_ql[Bsz*NH*Ssz*HD];
__device__ __nv_bfloat16 g_kh[Bsz*NH*Ssz*HD], g_kl[Bsz*NH*Ssz*HD];
__device__ __nv_bfloat16 g_vth[Bsz*NH*HD*Ssz], g_vtl[Bsz*NH*HD*Ssz];
// attention output, split, [m][EMB]
__device__ __nv_bfloat16 g_avh[M1*EMB], g_avl[M1*EMB];

// ---------------------------------------------------------------------------
// fp32 -> bf16 hi/lo split kernels (inputs only)
// ---------------------------------------------------------------------------
__device__ __forceinline__ void split4_store(const float4 f,
                                             __nv_bfloat162* hi, __nv_bfloat162* lo, int i)
{
    __nv_bfloat16 h0 = __float2bfloat16(f.x), h1 = __float2bfloat16(f.y);
    __nv_bfloat16 h2 = __float2bfloat16(f.z), h3 = __float2bfloat16(f.w);
    hi[2*i]   = __halves2bfloat162(h0, h1);
    hi[2*i+1] = __halves2bfloat162(h2, h3);
    lo[2*i]   = __halves2bfloat162(__float2bfloat16(f.x - __bfloat162float(h0)),
                                   __float2bfloat16(f.y - __bfloat162float(h1)));
    lo[2*i+1] = __halves2bfloat162(__float2bfloat16(f.z - __bfloat162float(h2)),
                                   __float2bfloat16(f.w - __bfloat162float(h3)));
}
__global__ void split_x(const float4* __restrict__ in) {
    int i = blockIdx.x * blockDim.x + threadIdx.x;
    if (i < (M1*INDIM)/4)
        split4_store(in[i], (__nv_bfloat162*)g_xh, (__nv_bfloat162*)g_xl, i);
}
__global__ void split_w(const float4* __restrict__ in) {
    int i = blockIdx.x * blockDim.x + threadIdx.x;
    if (i < (N1*INDIM)/4)
        split4_store(in[i], (__nv_bfloat162*)g_wh, (__nv_bfloat162*)g_wl, i);
}
__global__ void split_wo(const float4* __restrict__ in) {
    int i = blockIdx.x * blockDim.x + threadIdx.x;
    if (i < (EMB*EMB)/4)
        split4_store(in[i], (__nv_bfloat162*)g_woh, (__nv_bfloat162*)g_wol, i);
}

// ---------------------------------------------------------------------------
// HMMA GEMM mainloop (validated round 7): CTA 128x128, BK=32, 8 warps,
// double-buffered cp.async, smem rows 40 bf16 (80 B).
// ---------------------------------------------------------------------------
#define TILE_B 10240
#define GEMM_SMEM (8 * TILE_B)

__device__ __forceinline__ void load4_async(
    const __nv_bfloat16* ah, const __nv_bfloat16* al,
    const __nv_bfloat16* bh, const __nv_bfloat16* bl,
    int m0, int n0, int k0, uint32_t sb, int buf, int t)
{
    uint32_t base = sb + buf * 4 * TILE_B;
    #pragma unroll
    for (int i = 0; i < 2; i++) {
        int c  = t + i * 256;
        int r  = c >> 2;
        int kc = c & 3;
        size_t goffA = (size_t)(m0 + r) * 1024 + k0 + kc * 8;
        size_t goffB = (size_t)(n0 + r) * 1024 + k0 + kc * 8;
        uint32_t soff = (uint32_t)(r * 80 + kc * 16);
        CP_ASYNC16(base + 0*TILE_B + soff, ah + goffA);
        CP_ASYNC16(base + 1*TILE_B + soff, al + goffA);
        CP_ASYNC16(base + 2*TILE_B + soff, bh + goffB);
        CP_ASYNC16(base + 3*TILE_B + soff, bl + goffB);
    }
}

__device__ __forceinline__ void gemm_mainloop(
    const __nv_bfloat16* __restrict__ ah, const __nv_bfloat16* __restrict__ al,
    const __nv_bfloat16* __restrict__ bh, const __nv_bfloat16* __restrict__ bl,
    int m0, int n0, uint32_t sb, int t, float acc[4][4][4])
{
    const int lane = t & 31, wid = t >> 5;
    const int wm = (wid >> 2) * 64, wn = (wid & 3) * 32;

    #pragma unroll
    for (int a = 0; a < 4; a++)
        #pragma unroll
        for (int b = 0; b < 4; b++)
            #pragma unroll
            for (int e = 0; e < 4; e++)
                acc[a][b][e] = 0.f;

    load4_async(ah, al, bh, bl, m0, n0, 0, sb, 0, t);
    CP_COMMIT();

    const int arow = wm + (lane & 15);
    const int akd  = (lane & 16) >> 1;
    const int nrow = wn + (lane & 7) + ((lane & 16) >> 1);
    const int bkd  = (lane & 8);

    for (int ch = 0; ch < 32; ch++) {
        const int b = ch & 1;
        if (ch + 1 < 32) {
            load4_async(ah, al, bh, bl, m0, n0, (ch + 1) * 32, sb, 1 - b, t);
            CP_COMMIT();
            CP_WAIT1();
        } else {
            CP_WAIT0();
        }
        __syncthreads();

        const uint32_t base = sb + b * 4 * TILE_B;
        #pragma unroll
        for (int ks = 0; ks < 2; ks++) {
            const int kk = ks * 16;
            uint32_t ahf[4][4], alf[4][4], bhf[2][4], blf[2][4];
            #pragma unroll
            for (int mt = 0; mt < 4; mt++) {
                uint32_t off = (uint32_t)((arow + mt * 16) * 80 + (kk + akd) * 2);
                ldm_x4(ahf[mt], base + 0*TILE_B + off);
                ldm_x4(alf[mt], base + 1*TILE_B + off);
            }
            #pragma unroll
            for (int g = 0; g < 2; g++) {
                uint32_t off = (uint32_t)((nrow + g * 16) * 80 + (kk + bkd) * 2);
                ldm_x4(bhf[g], base + 2*TILE_B + off);
                ldm_x4(blf[g], base + 3*TILE_B + off);
            }
            #pragma unroll
            for (int mt = 0; mt < 4; mt++)
                #pragma unroll
                for (int nt = 0; nt < 4; nt++) {
                    const uint32_t* b2h = &bhf[nt >> 1][(nt & 1) * 2];
                    const uint32_t* b2l = &blf[nt >> 1][(nt & 1) * 2];
                    mma_bf16(acc[mt][nt], ahf[mt], b2h);
                    mma_bf16(acc[mt][nt], ahf[mt], b2l);
                    mma_bf16(acc[mt][nt], alf[mt], b2h);
                }
        }
        __syncthreads();
    }
}

// QKV projection: epilogue adds bias, applies padding mask, splits to bf16
// hi/lo and scatters q,k [b,h,s,d] and v TRANSPOSED [b,h,d,s].
__global__ __launch_bounds__(256) void qkv_mma(
    const float* __restrict__ bias, const int* __restrict__ pm)
{
    extern __shared__ __align__(16) char smem[];
    const uint32_t sb = smem_to_u32(smem);
    const int t = threadIdx.x, lane = t & 31, wid = t >> 5;
    const int wm = (wid >> 2) * 64, wn = (wid & 3) * 32;
    const int n0 = blockIdx.x * 128, m0 = blockIdx.y * 128;

    float acc[4][4][4];
    gemm_mainloop(g_xh, g_xl, g_wh, g_wl, m0, n0, sb, t, acc);

    const int lr = lane >> 2, lc = (lane & 3) * 2;
    #pragma unroll
    for (int mt = 0; mt < 4; mt++) {
        #pragma unroll
        for (int half = 0; half < 2; half++) {
            const int m = m0 + wm + mt * 16 + lr + half * 8;
            const int msk = pm[m];
            const int bb = m >> 11, s = m & 2047;
            #pragma unroll
            for (int nt = 0; nt < 4; nt++) {
                #pragma unroll
                for (int e = 0; e < 2; e++) {
                    const int n = n0 + wn + nt * 8 + lc + e;
                    float val = msk ? 0.0f : (acc[mt][nt][half * 2 + e] + bias[n]);
                    __nv_bfloat16 vh = __float2bfloat16(val);
                    __nv_bfloat16 vl = __float2bfloat16(val - __bfloat162float(vh));
                    int h  = n / 192;
                    int cc = n - h * 192;
                    if (cc < HD) {
                        int idx = ((bb * NH + h) * Ssz + s) * HD + cc;
                        g_qh[idx] = vh; g_ql[idx] = vl;
                    } else if (cc < 2*HD) {
                        int idx = ((bb * NH + h) * Ssz + s) * HD + cc - HD;
                        g_kh[idx] = vh; g_kl[idx] = vl;
                    } else {
                        int idx = ((bb * NH + h) * HD + cc - 2*HD) * Ssz + s;
                        g_vth[idx] = vh; g_vtl[idx] = vl;
                    }
                }
            }
        }
    }
}

// Output projection: out = attn_vals @ Wo^T + bo (A from g_avh/g_avl)
__global__ __launch_bounds__(256) void out_mma(
    const float* __restrict__ bias, float* __restrict__ C)
{
    extern __shared__ __align__(16) char smem[];
    const uint32_t sb = smem_to_u32(smem);
    const int t = threadIdx.x, lane = t & 31, wid = t >> 5;
    const int wm = (wid >> 2) * 64, wn = (wid & 3) * 32;
    const int n0 = blockIdx.x * 128, m0 = blockIdx.y * 128;

    float acc[4][4][4];
    gemm_mainloop(g_avh, g_avl, g_woh, g_wol, m0, n0, sb, t, acc);

    const int lr = lane >> 2, lc = (lane & 3) * 2;
    #pragma unroll
    for (int mt = 0; mt < 4; mt++) {
        #pragma unroll
        for (int half = 0; half < 2; half++) {
            const int m = m0 + wm + mt * 16 + lr + half * 8;
            #pragma unroll
            for (int nt = 0; nt < 4; nt++) {
                const int n = n0 + wn + nt * 8 + lc;
                float2 o;
                o.x = acc[mt][nt][half * 2 + 0] + bias[n];
                o.y = acc[mt][nt][half * 2 + 1] + bias[n + 1];
                *reinterpret_cast<float2*>(C + (size_t)m * EMB + n) = o;
            }
        }
    }
}

// ---------------------------------------------------------------------------
// Tensor-core banded attention. One block per (b,h,64-query tile), 256 thr.
// Score strip 320 keys (5 chunks of 64). All GEMMs via bf16-split HMMA.
// smem rows: 72 bf16 = 144 B (16B-aligned, conflict-free for ldmatrix).
// ---------------------------------------------------------------------------
#define SW   328          /* fp32 score row stride */
#define ARS  144          /* bf16 tile row stride in bytes */
#define OFF_QH  0
#define OFF_QL  9216
#define OFF_KH  18432     /* reused for V in PV phase */
#define OFF_KL  27648
#define OFF_PH  36864
#define OFF_PL  46080
#define OFF_SC  55296     /* 64*328*4 = 83968 */
#define OFF_INV 139264
#define ATTN_SMEM 139520

__global__ __launch_bounds__(256) void attn_kernel()
{
    extern __shared__ __align__(16) char smem[];
    const uint32_t sbase = smem_to_u32(smem);
    float* sc    = (float*)(smem + OFF_SC);
    float* inv_s = (float*)(smem + OFF_INV);

    const int t = threadIdx.x, lane = t & 31, w = t >> 5;
    const int b  = blockIdx.y >> 4, h = blockIdx.y & 15;
    const int qs = blockIdx.x * 64;
    const int kb = qs - PADW;

    const size_t qkbase = (size_t)(b * NH + h) * Ssz * HD;
    const size_t vbase  = (size_t)(b * NH + h) * HD * Ssz;

    // warp tiling: 4 warps over m (16 rows each), 2 warps over n (32 each)
    const int wm4 = (w >> 1) << 4;
    const int wn  = (w & 1) << 5;
    const int arow = wm4 + (lane & 15);
    const int akd  = (lane & 16) >> 1;
    const int nrow8 = (lane & 7) + ((lane & 16) >> 1);
    const int bkd  = (lane & 8);
    const int lr = lane >> 2, lc = (lane & 3) * 2;

    // ---- Load Q tile (64 x 64 bf16 hi/lo) ----
    {
        #pragma unroll
        for (int i = 0; i < 2; i++) {
            int u   = t + i * 256;          // 512 x 16B units
            int row = u >> 3;
            int c8  = (u & 7) * 8;
            uint32_t soff = (uint32_t)(row * ARS + c8 * 2);
            *reinterpret_cast<uint4*>(smem + OFF_QH + soff) =
                *reinterpret_cast<const uint4*>(g_qh + qkbase + (size_t)(qs + row) * HD + c8);
            *reinterpret_cast<uint4*>(smem + OFF_QL + soff) =
                *reinterpret_cast<const uint4*>(g_ql + qkbase + (size_t)(qs + row) * HD + c8);
        }
    }

    // ---- Score phase: 5 key chunks of 64 ----
    for (int ch = 0; ch < 5; ch++) {
        __syncthreads();   // prior chunk's reads of K buffers done; Q visible
        #pragma unroll
        for (int i = 0; i < 2; i++) {
            int u   = t + i * 256;
            int row = u >> 3;
            int c8  = (u & 7) * 8;
            int j   = kb + ch * 64 + row;
            uint32_t soff = (uint32_t)(row * ARS + c8 * 2);
            uint4 vh = make_uint4(0,0,0,0), vl = make_uint4(0,0,0,0);
            if (j >= 0 && j < Ssz) {
                vh = *reinterpret_cast<const uint4*>(g_kh + qkbase + (size_t)j * HD + c8);
                vl = *reinterpret_cast<const uint4*>(g_kl + qkbase + (size_t)j * HD + c8);
            }
            *reinterpret_cast<uint4*>(smem + OFF_KH + soff) = vh;
            *reinterpret_cast<uint4*>(smem + OFF_KL + soff) = vl;
        }
        __syncthreads();

        float acc[4][4];
        #pragma unroll
        for (int nt = 0; nt < 4; nt++)
            #pragma unroll
            for (int e = 0; e < 4; e++) acc[nt][e] = 0.f;

        #pragma unroll
        for (int ks = 0; ks < 4; ks++) {
            const int kk = ks * 16;
            uint32_t qh4[4], ql4[4], kh4[2][4], kl4[2][4];
            uint32_t aoff = (uint32_t)(arow * ARS + (kk + akd) * 2);
            ldm_x4(qh4, sbase + OFF_QH + aoff);
            ldm_x4(ql4, sbase + OFF_QL + aoff);
            #pragma unroll
            for (int g = 0; g < 2; g++) {
                uint32_t boff = (uint32_t)((wn + nrow8 + g * 16) * ARS + (kk + bkd) * 2);
                ldm_x4(kh4[g], sbase + OFF_KH + boff);
                ldm_x4(kl4[g], sbase + OFF_KL + boff);
            }
            #pragma unroll
            for (int nt = 0; nt < 4; nt++) {
                const uint32_t* b2h = &kh4[nt >> 1][(nt & 1) * 2];
                const uint32_t* b2l = &kl4[nt >> 1][(nt & 1) * 2];
                mma_bf16(acc[nt], qh4, b2h);
                mma_bf16(acc[nt], qh4, b2l);
                mma_bf16(acc[nt], ql4, b2h);
            }
        }
        // store raw scores
        #pragma unroll
        for (int nt = 0; nt < 4; nt++) {
            #pragma unroll
            for (int half = 0; half < 2; half++) {
                int r = wm4 + lr + half * 8;
                int c = ch * 64 + wn + nt * 8 + lc;
                sc[r * SW + c]     = acc[nt][half * 2 + 0];
                sc[r * SW + c + 1] = acc[nt][half * 2 + 1];
            }
        }
    }
    __syncthreads();

    // ---- Softmax over 320-wide band strip (4 lanes per query row) ----
    {
        const int r = t >> 2, g = t & 3;
        const float scale = 0.125f;
        float mx = -1e30f;
        for (int c = g; c < 320; c += 4) {
            int j = kb + c;
            if (j >= 0 && j < Ssz && c >= r && c <= r + 256)
                mx = fmaxf(mx, sc[r * SW + c]);
        }
        mx = fmaxf(mx, __shfl_xor_sync(0xffffffffu, mx, 1));
        mx = fmaxf(mx, __shfl_xor_sync(0xffffffffu, mx, 2));
        float mxs = mx * scale;
        float sum = 0.f;
        for (int c = g; c < 320; c += 4) {
            int j = kb + c;
            float e = 0.f;
            if (j >= 0 && j < Ssz && c >= r && c <= r + 256)
                e = __expf(sc[r * SW + c] * scale - mxs);
            sc[r * SW + c] = e;
            sum += e;
        }
        sum += __shfl_xor_sync(0xffffffffu, sum, 1);
        sum += __shfl_xor_sync(0xffffffffu, sum, 2);
        if (g == 0) inv_s[r] = 1.0f / sum;
    }

    // ---- PV phase: out[64 x 64] = P[64 x 320] @ V[320 x 64] (split HMMA) ----
    float acc2[4][4];
    #pragma unroll
    for (int nt = 0; nt < 4; nt++)
        #pragma unroll
        for (int e = 0; e < 4; e++) acc2[nt][e] = 0.f;

    for (int ch = 0; ch < 5; ch++) {
        __syncthreads();   // softmax done / prior chunk's V,P reads done
        // load V^T chunk [64 d][64 keys] into K buffers
        #pragma unroll
        for (int i = 0; i < 2; i++) {
            int u   = t + i * 256;
            int row = u >> 3;               // d
            int c8  = (u & 7) * 8;          // key offset within chunk
            int j0  = kb + ch * 64 + c8;
            uint32_t soff = (uint32_t)(row * ARS + c8 * 2);
            uint4 vh = make_uint4(0,0,0,0), vl = make_uint4(0,0,0,0);
            if (j0 >= 0 && j0 < Ssz) {
                vh = *reinterpret_cast<const uint4*>(g_vth + vbase + (size_t)row * Ssz + j0);
                vl = *reinterpret_cast<const uint4*>(g_vtl + vbase + (size_t)row * Ssz + j0);
            }
            *reinterpret_cast<uint4*>(smem + OFF_KH + soff) = vh;
            *reinterpret_cast<uint4*>(smem + OFF_KL + soff) = vl;
        }
        // convert P chunk (unnormalized exp) to bf16 hi/lo
        #pragma unroll
        for (int i = 0; i < 8; i++) {
            int p  = t + i * 256;           // 2048 pairs
            int r  = p >> 5;
            int c2 = (p & 31) * 2;
            float e0 = sc[r * SW + ch * 64 + c2];
            float e1 = sc[r * SW + ch * 64 + c2 + 1];
            __nv_bfloat16 h0 = __float2bfloat16(e0), h1 = __float2bfloat16(e1);
            __nv_bfloat162 ph = __halves2bfloat162(h0, h1);
            __nv_bfloat162 pl = __halves2bfloat162(
                __float2bfloat16(e0 - __bfloat162float(h0)),
                __float2bfloat16(e1 - __bfloat162float(h1)));
            *reinterpret_cast<__nv_bfloat162*>(smem + OFF_PH + r * ARS + c2 * 2) = ph;
            *reinterpret_cast<__nv_bfloat162*>(smem + OFF_PL + r * ARS + c2 * 2) = pl;
        }
        __syncthreads();

        #pragma unroll
        for (int ks = 0; ks < 4; ks++) {
            const int kk = ks * 16;
            uint32_t ph4[4], pl4[4], vh4[2][4], vl4[2][4];
            uint32_t aoff = (uint32_t)(arow * ARS + (kk + akd) * 2);
            ldm_x4(ph4, sbase + OFF_PH + aoff);
            ldm_x4(pl4, sbase + OFF_PL + aoff);
            #pragma unroll
            for (int g = 0; g < 2; g++) {
                uint32_t boff = (uint32_t)((wn + nrow8 + g * 16) * ARS + (kk + bkd) * 2);
                ldm_x4(vh4[g], sbase + OFF_KH + boff);
                ldm_x4(vl4[g], sbase + OFF_KL + boff);
            }
            #pragma unroll
            for (int nt = 0; nt < 4; nt++) {
                const uint32_t* b2h = &vh4[nt >> 1][(nt & 1) * 2];
                const uint32_t* b2l = &vl4[nt >> 1][(nt & 1) * 2];
                mma_bf16(acc2[nt], ph4, b2h);
                mma_bf16(acc2[nt], ph4, b2l);
                mma_bf16(acc2[nt], pl4, b2h);
            }
        }
    }
    __syncthreads();

    // ---- Epilogue: normalize, split to bf16 hi/lo, write [m][EMB] ----
    #pragma unroll
    for (int half = 0; half < 2; half++) {
        const int r  = wm4 + lr + half * 8;
        const float is = inv_s[r];
        const size_t rowbase = (size_t)(b * Ssz + qs + r) * EMB + h * HD;
        #pragma unroll
        for (int nt = 0; nt < 4; nt++) {
            #pragma unroll
            for (int e = 0; e < 2; e++) {
                const int d = wn + nt * 8 + lc + e;
                float val = acc2[nt][half * 2 + e] * is;
                __nv_bfloat16 vh = __float2bfloat16(val);
                g_avh[rowbase + d] = vh;
                g_avl[rowbase + d] = __float2bfloat16(val - __bfloat162float(vh));
            }
        }
    }
}

// ---------------------------------------------------------------------------
extern "C" void kernel_launch(void* const* d_in, const int* in_sizes, int n_in,
                              void* d_out, int out_size)
{
    const float* x    = (const float*)d_in[0];
    const int*   pm   = (const int*)  d_in[1];
    const float* Wqkv = (const float*)d_in[2];
    const float* bqkv = (const float*)d_in[3];
    const float* Wo   = (const float*)d_in[4];
    const float* bo   = (const float*)d_in[5];
    float* out = (float*)d_out;

    cudaFuncSetAttribute(attn_kernel,
                         cudaFuncAttributeMaxDynamicSharedMemorySize, ATTN_SMEM);
    cudaFuncSetAttribute(qkv_mma,
                         cudaFuncAttributeMaxDynamicSharedMemorySize, GEMM_SMEM);
    cudaFuncSetAttribute(out_mma,
                         cudaFuncAttributeMaxDynamicSharedMemorySize, GEMM_SMEM);

    split_x <<<(M1*INDIM/4 + 255)/256, 256>>>((const float4*)x);
    split_w <<<(N1*INDIM/4 + 255)/256, 256>>>((const float4*)Wqkv);
    split_wo<<<(EMB*EMB/4  + 255)/256, 256>>>((const float4*)Wo);

    qkv_mma<<<dim3(N1/128, M1/128), 256, GEMM_SMEM>>>(bqkv, pm);

    attn_kernel<<<dim3(Ssz/64, Bsz*NH), 256, ATTN_SMEM>>>();

    out_mma<<<dim3(EMB/128, M1/128), 256, GEMM_SMEM>>>(bo, out);
}